// round 11
// baseline (speedup 1.0000x reference)
#include <cuda_runtime.h>
#include <math.h>

#define MM 63
#define NN 127
#define BB 256
#define OUT_LOSS (4*BB*NN)
#define NI4 16            // capacity: packed col words per check row (pad c=127)
#define NJ4 10            // capacity: packed check words per column (pad m=63)
#define ROTS 9            // padded stride for rot/b1R

__device__ float    g_partials[BB / 2];
__device__ unsigned g_done = 0;

#define HALF_BAR(row) asm volatile("bar.sync %0, 512;" :: "r"((row) + 1) : "memory")

__device__ __forceinline__ int sigma_apply(int c, int sh, int v) {
    int j = c - sh; if (j < 0) j += NN;
    return v ? ((2 * j >= NN) ? 2 * j - NN : 2 * j) : j;
}

__global__ __launch_bounds__(1024)
void decode_kernel(const float* __restrict__ soft_in,
                   const int*   __restrict__ labels,
                   const float* __restrict__ H,
                   const float* __restrict__ cw,
                   float*       __restrict__ out) {
    __shared__ float    s_soft[2][NN + 1];
    __shared__ float    s_rot[2][128 * ROTS];
    __shared__ float    s_b1R[2][64 * ROTS];
    __shared__ float    s_corr[2][NN + 1];
    __shared__ unsigned s_cols4[NI4 * 64];   // [i4*64+m], pre-padded
    __shared__ unsigned s_rows4[NJ4 * NN];   // [j4*127+c], pre-padded
    __shared__ unsigned s_mask[64][4];       // row bitmasks of H
    __shared__ float    s_red[32];
    __shared__ float    s_sp;
    __shared__ int      s_maxA, s_maxB;      // uniform loop bounds
    __shared__ int      s_last;

    const int tid  = threadIdx.x;
    const int row  = tid >> 9;
    const int rtid = tid & 511;
    const int b    = blockIdx.x * 2 + row;
    const int wid  = tid >> 5, lane = tid & 31;

    // ---- block 1: staging, ballots, pad-fill ----
    if (rtid < NN) {
        float v = soft_in[b * NN + rtid];
        s_soft[row][rtid] = v;
        out[b * NN + rtid] = v;               // outs[0]
        s_corr[row][rtid] = 0.f;
    }
    if (rtid == NN) s_soft[row][NN] = 1e38f;
    if (rtid < 8)   s_b1R[row][63 * ROTS + rtid] = 0.f;
    if (tid == 0) {
        float x = cw[0];
        s_sp = (x > 0.f) ? (x + log1pf(expf(-x))) : log1pf(expf(x));
        s_maxA = 0; s_maxB = 0;
    }
    s_cols4[tid] = 0x7F7F7F7Fu;                         // 1024 words
    for (int i = tid; i < NJ4 * NN; i += 1024) s_rows4[i] = 0x3F3F3F3Fu;
    for (int m = wid; m < MM; m += 32) {
        float v0 = H[m * NN + lane];
        float v1 = H[m * NN + lane + 32];
        float v2 = H[m * NN + lane + 64];
        float v3 = (lane + 96 < NN) ? H[m * NN + lane + 96] : 0.f;
        unsigned b0 = __ballot_sync(~0u, v0 != 0.f);
        unsigned b1 = __ballot_sync(~0u, v1 != 0.f);
        unsigned b2 = __ballot_sync(~0u, v2 != 0.f);
        unsigned b3 = __ballot_sync(~0u, v3 != 0.f);
        if (lane == 0) {
            s_mask[m][0] = b0; s_mask[m][1] = b1;
            s_mask[m][2] = b2; s_mask[m][3] = b3;
        }
    }
    __syncthreads();

    // ---- block 2: list build over pre-padded arrays + max bounds ----
    if (tid < MM) {                 // row lists
        int m = tid, cnt = 0, i4 = 0;
        unsigned w = 0;
        #pragma unroll
        for (int q = 0; q < 4; ++q) {
            unsigned msk = s_mask[m][q];
            while (msk) {
                int bit = __ffs(msk) - 1;
                msk &= msk - 1;
                w |= (unsigned)(q * 32 + bit) << (8 * (cnt & 3));
                if ((++cnt & 3) == 0) { s_cols4[i4 * 64 + m] = w; ++i4; w = 0; }
            }
        }
        if (cnt & 3) {
            for (int k = cnt & 3; k < 4; ++k) w |= 127u << (8 * k);
            s_cols4[i4 * 64 + m] = w;
        }
        atomicMax(&s_maxA, (cnt + 3) >> 2);
    }
    if (tid >= 512 && tid < 512 + NN) {   // column lists
        int c = tid - 512;
        int word = c >> 5, bit = c & 31;
        int rc = 0, j4 = 0;
        unsigned w = 0;
        for (int m = 0; m < MM; ++m) {
            if ((s_mask[m][word] >> bit) & 1u) {
                w |= (unsigned)m << (8 * (rc & 3));
                if ((++rc & 3) == 0) { s_rows4[j4 * NN + c] = w; ++j4; w = 0; }
            }
        }
        if (rc & 3) {
            for (int k = rc & 3; k < 4; ++k) w |= 63u << (8 * k);
            s_rows4[j4 * NN + c] = w;
        }
        atomicMax(&s_maxB, (rc + 3) >> 2);
    }
    __syncthreads();

    // ---- rot init + identities ----
    {
        int j = rtid, c = j >> 3, t = j & 7;
        s_rot[row][c * ROTS + t] =
            (c < NN) ? s_soft[row][sigma_apply(c, (t & 3) * 31, t >> 2)] : 1e38f;
        j = rtid + 512; c = j >> 3; t = j & 7;
        s_rot[row][c * ROTS + t] =
            (c < NN) ? s_soft[row][sigma_apply(c, (t & 3) * 31, t >> 2)] : 1e38f;
    }
    const int  m_a    = rtid >> 3;           // 63 = pad row (all-pad words)
    const int  t_a    = rtid & 7;
    const bool validA = (m_a < MM);
    const int  maxA   = s_maxA;              // racy read? no: set in block2, but...
    __syncthreads();
    const int  maxA2  = s_maxA;              // safe uniform bounds after barrier
    const int  maxB   = s_maxB;
    (void)maxA;

    const float coefA = s_sp * ((t_a >> 2) ? 2.0f : 1.0f);

    // Phase B identity
    const int t_b = rtid & 7;
    const int n0  = rtid >> 3;
    int cB[2]; bool vB[2];
    #pragma unroll
    for (int r = 0; r < 2; ++r) {
        int n = n0 + 64 * r;
        vB[r] = (n < NN);
        int cb = (t_b >> 2) ? ((n * 64) % NN) : n;
        int c  = cb + (t_b & 3) * 31; if (c >= NN) c -= NN;
        cB[r]  = vB[r] ? c : 0;
    }

    for (int it = 0; it < 3; ++it) {
        // ---------- Phase A: uniform-trip top-2 + argmin + parity ----------
        if (validA) {
            const unsigned* rt = (const unsigned*)&s_rot[row][t_a];
            unsigned k1a = ~0u, k2a = ~0u, k1b = ~0u, k2b = ~0u, sx = 0u;
            #pragma unroll 4
            for (int i4 = 0; i4 < maxA2; ++i4) {
                unsigned w = s_cols4[i4 * 64 + m_a];
                int c0 = w & 255, c1 = (w >> 8) & 255, c2 = (w >> 16) & 255, c3 = w >> 24;
                unsigned u0 = rt[c0 * ROTS], u1 = rt[c1 * ROTS];
                unsigned u2 = rt[c2 * ROTS], u3 = rt[c3 * ROTS];
                sx ^= u0 ^ u1 ^ u2 ^ u3;
                unsigned key0 = (u0 & 0x7FFFFF80u) | (unsigned)c0;
                unsigned key1 = (u1 & 0x7FFFFF80u) | (unsigned)c1;
                unsigned key2 = (u2 & 0x7FFFFF80u) | (unsigned)c2;
                unsigned key3 = (u3 & 0x7FFFFF80u) | (unsigned)c3;
                k2a = min(k2a, max(key0, k1a)); k1a = min(k1a, key0);
                k2b = min(k2b, max(key1, k1b)); k1b = min(k1b, key1);
                k2a = min(k2a, max(key2, k1a)); k1a = min(k1a, key2);
                k2b = min(k2b, max(key3, k1b)); k1b = min(k1b, key3);
            }
            // pad elements: c=127 -> rt[127*ROTS]=huge, sign+, never min; sx parity
            // picks up huge's sign bit (0) -> unchanged.
            unsigned k1 = min(k1a, k1b);
            unsigned k2 = min(min(k2a, k2b), max(k1a, k1b));
            unsigned a1 = k1 & 0x7FFFFF80u;
            float min1 = __uint_as_float(a1);
            float min2 = __uint_as_float(k2 & 0x7FFFFF80u);
            int   cmin = (int)(k1 & 127u);
            float sg   = a1 ? ((sx & 0x80000000u) ? -1.f : 1.f) : 0.f;
            float cs   = coefA * sg;
            s_b1R[row][m_a * ROTS + t_a] = cs * min1;
            float ym = s_rot[row][cmin * ROTS + t_a];
            float s1 = (ym > 0.f) ? 1.f : ((ym < 0.f) ? -1.f : 0.f);
            int  nstar = sigma_apply(cmin, (t_a & 3) * 31, t_a >> 2);
            atomicAdd(&s_corr[row][nstar], s1 * cs * (min2 - min1));
        }
        HALF_BAR(row);

        // ---------- Phase B: uniform-trip gather + fused update ----------
        float acc[2], yv[2];
        const float* bt = &s_b1R[row][t_b];
        #pragma unroll
        for (int r = 0; r < 2; ++r) {
            float a = 0.f; yv[r] = 0.f;
            {
                int c = cB[r];
                float sum = 0.f;
                #pragma unroll 2
                for (int j4 = 0; j4 < maxB; ++j4) {
                    unsigned w = s_rows4[j4 * NN + c];
                    sum += bt[(w & 255) * ROTS] + bt[((w >> 8) & 255) * ROTS]
                         + bt[((w >> 16) & 255) * ROTS] + bt[(w >> 24) * ROTS];
                }
                float y = s_soft[row][vB[r] ? (n0 + 64 * r) : 0];
                yv[r] = y;
                float s1 = (y > 0.f) ? 1.f : ((y < 0.f) ? -1.f : 0.f);
                a = s1 * sum;
                if (t_b == 0 && vB[r]) a += s_corr[row][n0 + 64 * r];
            }
            acc[r] = a;
        }
        #pragma unroll
        for (int r = 0; r < 2; ++r) {
            acc[r] += __shfl_xor_sync(0xffffffffu, acc[r], 1);
            acc[r] += __shfl_xor_sync(0xffffffffu, acc[r], 2);
            acc[r] += __shfl_xor_sync(0xffffffffu, acc[r], 4);
        }
        #pragma unroll
        for (int r = 0; r < 2; ++r) {
            if (vB[r]) {
                int n = n0 + 64 * r;
                float ns = yv[r] + acc[r] * (1.0f / 12.0f);
                s_rot[row][cB[r] * ROTS + t_b] = ns;
                if (t_b == 0) {
                    s_corr[row][n] = 0.f;
                    s_soft[row][n] = ns;
                    out[(it + 1) * BB * NN + b * NN + n] = ns;
                }
            }
        }
        HALF_BAR(row);
    }

    // ---------- loss: block partial + last-CTA finalize ----------
    float part = 0.f;
    if (rtid < NN) {
        float x   = s_soft[row][rtid];
        float lf  = (float)labels[b * NN + rtid];
        float sgn = (x > 0.f) ? 1.f : ((x < 0.f) ? -1.f : 0.f);
        float w   = (sgn != 1.f - 2.f * lf) ? 2.0f : 1.0f;
        float z   = -x;
        part = w * (fmaxf(z, 0.f) - z * lf + log1pf(expf(-fabsf(z))));
    }
    #pragma unroll
    for (int off = 16; off; off >>= 1)
        part += __shfl_down_sync(0xffffffffu, part, off);
    if ((tid & 31) == 0) s_red[tid >> 5] = part;
    __syncthreads();
    if (tid < 32) {
        part = s_red[tid];
        #pragma unroll
        for (int off = 16; off; off >>= 1)
            part += __shfl_down_sync(0xffffffffu, part, off);
        if (tid == 0) {
            g_partials[blockIdx.x] = part;
            __threadfence();
            unsigned old = atomicAdd(&g_done, 1u);
            s_last = (old == (unsigned)(gridDim.x - 1));
        }
    }
    __syncthreads();
    if (s_last) {
        __threadfence();
        float v = (tid < BB / 2) ? g_partials[tid] : 0.f;
        #pragma unroll
        for (int off = 16; off; off >>= 1)
            v += __shfl_down_sync(0xffffffffu, v, off);
        if (tid < BB / 2 && (tid & 31) == 0) s_red[tid >> 5] = v;
        __syncthreads();
        if (tid == 0) {
            out[OUT_LOSS] = s_red[0] + s_red[1] + s_red[2] + s_red[3];
            g_done = 0;                      // self-restore for next replay
        }
    }
}

extern "C" void kernel_launch(void* const* d_in, const int* in_sizes, int n_in,
                              void* d_out, int out_size) {
    const float* soft = (const float*)d_in[0];
    const int*   lab  = (const int*)d_in[1];
    const float* H    = (const float*)d_in[2];
    const float* cw   = (const float*)d_in[3];
    float* out = (float*)d_out;

    decode_kernel<<<BB / 2, 1024>>>(soft, lab, H, cw, out);
}

// round 12
// speedup vs baseline: 1.1104x; 1.1104x over previous
#include <cuda_runtime.h>
#include <math.h>

#define MM 63
#define NN 127
#define BB 256
#define OUT_LOSS (4*BB*NN)
#define NI4 16            // capacity: packed col words per check row (pad c=127)
#define NJ4 10            // capacity: packed check words per column (pad m=63)
#define ROTS 9            // padded stride for rot/b1R

__device__ float    g_partials[BB / 2];
__device__ unsigned g_done = 0;

#define HALF_BAR(row) asm volatile("bar.sync %0, 512;" :: "r"((row) + 1) : "memory")

__device__ __forceinline__ int sigma_apply(int c, int sh, int v) {
    int j = c - sh; if (j < 0) j += NN;
    return v ? ((2 * j >= NN) ? 2 * j - NN : 2 * j) : j;
}

__global__ __launch_bounds__(1024)
void decode_kernel(const float* __restrict__ soft_in,
                   const int*   __restrict__ labels,
                   const float* __restrict__ H,
                   const float* __restrict__ cw,
                   float*       __restrict__ out) {
    __shared__ float    s_soft[2][NN + 1];
    __shared__ float    s_rot[2][128 * ROTS];
    __shared__ float    s_b1R[2][64 * ROTS];
    __shared__ float    s_corr[2][NN + 1];
    __shared__ unsigned s_cols4[NI4 * 64];   // [i4*64+m], pre-padded 0x7F
    __shared__ unsigned s_rows4[NJ4 * NN];   // [j4*127+c], pre-padded 0x3F
    __shared__ unsigned s_mask[64][4];       // row bitmasks of H
    __shared__ unsigned s_cmask[128][2];     // column bitmasks (transposed)
    __shared__ int      s_pref[64][4];       // per-row word popc prefixes
    __shared__ int      s_cnt4[64];
    __shared__ float    s_red[32];
    __shared__ float    s_sp;
    __shared__ int      s_maxB;
    __shared__ int      s_last;

    const int tid  = threadIdx.x;
    const int row  = tid >> 9;
    const int rtid = tid & 511;
    const int b    = blockIdx.x * 2 + row;
    const int wid  = tid >> 5, lane = tid & 31;

    // ---- P0: staging, pad fills, row-mask ballots ----
    if (rtid < NN) {
        float v = soft_in[b * NN + rtid];
        s_soft[row][rtid] = v;
        out[b * NN + rtid] = v;               // outs[0]
        s_corr[row][rtid] = 0.f;
    }
    if (rtid == NN) s_soft[row][NN] = 1e38f;
    if (rtid < 8)   s_b1R[row][63 * ROTS + rtid] = 0.f;
    if (tid == 0) { s_maxB = 0;
        float x = cw[0];
        s_sp = (x > 0.f) ? (x + log1pf(expf(-x))) : log1pf(expf(x));
    }
    s_cols4[tid] = 0x7F7F7F7Fu;                         // 1024 words
    for (int i = tid; i < NJ4 * NN; i += 1024) s_rows4[i] = 0x3F3F3F3Fu;
    for (int m = wid; m < MM; m += 32) {
        float v0 = H[m * NN + lane];
        float v1 = H[m * NN + lane + 32];
        float v2 = H[m * NN + lane + 64];
        float v3 = (lane + 96 < NN) ? H[m * NN + lane + 96] : 0.f;
        unsigned b0 = __ballot_sync(~0u, v0 != 0.f);
        unsigned b1 = __ballot_sync(~0u, v1 != 0.f);
        unsigned b2 = __ballot_sync(~0u, v2 != 0.f);
        unsigned b3 = __ballot_sync(~0u, v3 != 0.f);
        if (lane == 0) {
            s_mask[m][0] = b0; s_mask[m][1] = b1;
            s_mask[m][2] = b2; s_mask[m][3] = b3;
        }
    }
    __syncthreads();

    // ---- P1: row prefixes/counts (tid<63) + ballot transpose (warps 16-31) ----
    if (tid < MM) {
        int m = tid;
        unsigned w0 = s_mask[m][0], w1 = s_mask[m][1];
        unsigned w2 = s_mask[m][2], w3 = s_mask[m][3];
        int p0 = __popc(w0), p1 = __popc(w1), p2 = __popc(w2);
        s_pref[m][0] = 0; s_pref[m][1] = p0;
        s_pref[m][2] = p0 + p1; s_pref[m][3] = p0 + p1 + p2;
        s_cnt4[m] = (p0 + p1 + p2 + __popc(w3) + 3) >> 2;
    }
    if (wid >= 16) {
        for (int op = wid - 16; op < 254; op += 16) {
            int c = op >> 1, q = op & 1;
            int m_l = q * 32 + lane;
            unsigned v = (m_l < MM) ? ((s_mask[m_l][c >> 5] >> (c & 31)) & 1u) : 0u;
            unsigned bal = __ballot_sync(~0u, v);
            if (lane == 0) s_cmask[c][q] = bal;
        }
    }
    __syncthreads();

    // ---- P2: rank-based extraction (all warps) + rot init ----
    {   // row lists: thread (m = tid>>4, nb = tid&15) covers 8 columns
        int m = tid >> 4, nb = tid & 15;
        if (m < MM) {
            int q = nb >> 2, base = (nb & 3) * 8;
            unsigned msk = s_mask[m][q];
            int pc = s_pref[m][q] + __popc(msk & ((1u << base) - 1u));
            unsigned char* dst = (unsigned char*)s_cols4;
            #pragma unroll
            for (int k = 0; k < 8; ++k) {
                if ((msk >> (base + k)) & 1u) {
                    int r = pc++;
                    dst[((r >> 2) * 64 + m) * 4 + (r & 3)] = (unsigned char)(q * 32 + base + k);
                }
            }
        }
    }
    {   // column lists: thread (c = tid>>3, mb = tid&7) covers 8 checks
        int c = tid >> 3, mb = tid & 7;
        if (c < NN) {
            int q = mb >> 2, base = (mb & 3) * 8;
            unsigned msk = s_cmask[c][q];
            int pc = (q ? __popc(s_cmask[c][0]) : 0) + __popc(msk & ((1u << base) - 1u));
            unsigned char* dst = (unsigned char*)s_rows4;
            #pragma unroll
            for (int k = 0; k < 8; ++k) {
                if ((msk >> (base + k)) & 1u) {
                    int r = pc++;
                    dst[((r >> 2) * NN + c) * 4 + (r & 3)] = (unsigned char)(q * 32 + base + k);
                }
            }
            if (mb == 0) {
                int rc = __popc(s_cmask[c][0]) + __popc(s_cmask[c][1]);
                atomicMax(&s_maxB, (rc + 3) >> 2);
            }
        }
    }
    {   // rot init: rot[c*ROTS+t] = soft[sigma_t(c)]
        int j = rtid, c = j >> 3, t = j & 7;
        s_rot[row][c * ROTS + t] =
            (c < NN) ? s_soft[row][sigma_apply(c, (t & 3) * 31, t >> 2)] : 1e38f;
        j = rtid + 512; c = j >> 3; t = j & 7;
        s_rot[row][c * ROTS + t] =
            (c < NN) ? s_soft[row][sigma_apply(c, (t & 3) * 31, t >> 2)] : 1e38f;
    }
    const int  m_a    = rtid >> 3;
    const int  t_a    = rtid & 7;
    const bool validA = (m_a < MM);
    __syncthreads();

    const float coefA = s_sp * ((t_a >> 2) ? 2.0f : 1.0f);
    const int   cntA  = validA ? s_cnt4[m_a] : 0;
    const int   maxB  = s_maxB;

    // Phase B identity
    const int t_b = rtid & 7;
    const int n0  = rtid >> 3;
    int cB[2]; bool vB[2];
    #pragma unroll
    for (int r = 0; r < 2; ++r) {
        int n = n0 + 64 * r;
        vB[r] = (n < NN);
        int cb = (t_b >> 2) ? ((n * 64) % NN) : n;
        int c  = cb + (t_b & 3) * 31; if (c >= NN) c -= NN;
        cB[r]  = vB[r] ? c : 0;
    }

    for (int it = 0; it < 3; ++it) {
        // ---------- Phase A: top-2 + argmin + parity ----------
        if (validA) {
            const unsigned* rt = (const unsigned*)&s_rot[row][t_a];
            unsigned k1a = ~0u, k2a = ~0u, k1b = ~0u, k2b = ~0u, sx = 0u;
            #pragma unroll 4
            for (int i4 = 0; i4 < cntA; ++i4) {
                unsigned w = s_cols4[i4 * 64 + m_a];
                int c0 = w & 255, c1 = (w >> 8) & 255, c2 = (w >> 16) & 255, c3 = w >> 24;
                unsigned u0 = rt[c0 * ROTS], u1 = rt[c1 * ROTS];
                unsigned u2 = rt[c2 * ROTS], u3 = rt[c3 * ROTS];
                sx ^= u0 ^ u1 ^ u2 ^ u3;
                unsigned key0 = (u0 & 0x7FFFFF80u) | (unsigned)c0;
                unsigned key1 = (u1 & 0x7FFFFF80u) | (unsigned)c1;
                unsigned key2 = (u2 & 0x7FFFFF80u) | (unsigned)c2;
                unsigned key3 = (u3 & 0x7FFFFF80u) | (unsigned)c3;
                k2a = min(k2a, max(key0, k1a)); k1a = min(k1a, key0);
                k2b = min(k2b, max(key1, k1b)); k1b = min(k1b, key1);
                k2a = min(k2a, max(key2, k1a)); k1a = min(k1a, key2);
                k2b = min(k2b, max(key3, k1b)); k1b = min(k1b, key3);
            }
            unsigned k1 = min(k1a, k1b);
            unsigned k2 = min(min(k2a, k2b), max(k1a, k1b));
            unsigned a1 = k1 & 0x7FFFFF80u;
            float min1 = __uint_as_float(a1);
            float min2 = __uint_as_float(k2 & 0x7FFFFF80u);
            int   cmin = (int)(k1 & 127u);
            float sg   = a1 ? ((sx & 0x80000000u) ? -1.f : 1.f) : 0.f;
            float cs   = coefA * sg;
            s_b1R[row][m_a * ROTS + t_a] = cs * min1;
            float ym = s_rot[row][cmin * ROTS + t_a];
            float s1 = (ym > 0.f) ? 1.f : ((ym < 0.f) ? -1.f : 0.f);
            int  nstar = sigma_apply(cmin, (t_a & 3) * 31, t_a >> 2);
            atomicAdd(&s_corr[row][nstar], s1 * cs * (min2 - min1));
        }
        HALF_BAR(row);

        // ---------- Phase B: gather + fused update + rot refresh ----------
        float acc[2], yv[2];
        const float* bt = &s_b1R[row][t_b];
        #pragma unroll
        for (int r = 0; r < 2; ++r) {
            float a = 0.f; yv[r] = 0.f;
            {
                int c = cB[r];
                float sum = 0.f;
                #pragma unroll 2
                for (int j4 = 0; j4 < maxB; ++j4) {
                    unsigned w = s_rows4[j4 * NN + c];
                    sum += bt[(w & 255) * ROTS] + bt[((w >> 8) & 255) * ROTS]
                         + bt[((w >> 16) & 255) * ROTS] + bt[(w >> 24) * ROTS];
                }
                float y = s_soft[row][vB[r] ? (n0 + 64 * r) : 0];
                yv[r] = y;
                float s1 = (y > 0.f) ? 1.f : ((y < 0.f) ? -1.f : 0.f);
                a = s1 * sum;
                if (t_b == 0 && vB[r]) a += s_corr[row][n0 + 64 * r];
            }
            acc[r] = a;
        }
        #pragma unroll
        for (int r = 0; r < 2; ++r) {
            acc[r] += __shfl_xor_sync(0xffffffffu, acc[r], 1);
            acc[r] += __shfl_xor_sync(0xffffffffu, acc[r], 2);
            acc[r] += __shfl_xor_sync(0xffffffffu, acc[r], 4);
        }
        #pragma unroll
        for (int r = 0; r < 2; ++r) {
            if (vB[r]) {
                int n = n0 + 64 * r;
                float ns = yv[r] + acc[r] * (1.0f / 12.0f);
                s_rot[row][cB[r] * ROTS + t_b] = ns;
                if (t_b == 0) {
                    s_corr[row][n] = 0.f;
                    s_soft[row][n] = ns;
                    out[(it + 1) * BB * NN + b * NN + n] = ns;
                }
            }
        }
        HALF_BAR(row);
    }

    // ---------- loss: block partial + last-CTA finalize ----------
    float part = 0.f;
    if (rtid < NN) {
        float x   = s_soft[row][rtid];
        float lf  = (float)labels[b * NN + rtid];
        float sgn = (x > 0.f) ? 1.f : ((x < 0.f) ? -1.f : 0.f);
        float w   = (sgn != 1.f - 2.f * lf) ? 2.0f : 1.0f;
        float z   = -x;
        part = w * (fmaxf(z, 0.f) - z * lf + log1pf(expf(-fabsf(z))));
    }
    #pragma unroll
    for (int off = 16; off; off >>= 1)
        part += __shfl_down_sync(0xffffffffu, part, off);
    if ((tid & 31) == 0) s_red[tid >> 5] = part;
    __syncthreads();
    if (tid < 32) {
        part = s_red[tid];
        #pragma unroll
        for (int off = 16; off; off >>= 1)
            part += __shfl_down_sync(0xffffffffu, part, off);
        if (tid == 0) {
            g_partials[blockIdx.x] = part;
            __threadfence();
            unsigned old = atomicAdd(&g_done, 1u);
            s_last = (old == (unsigned)(gridDim.x - 1));
        }
    }
    __syncthreads();
    if (s_last) {
        __threadfence();
        float v = (tid < BB / 2) ? g_partials[tid] : 0.f;
        #pragma unroll
        for (int off = 16; off; off >>= 1)
            v += __shfl_down_sync(0xffffffffu, v, off);
        if (tid < BB / 2 && (tid & 31) == 0) s_red[tid >> 5] = v;
        __syncthreads();
        if (tid == 0) {
            out[OUT_LOSS] = s_red[0] + s_red[1] + s_red[2] + s_red[3];
            g_done = 0;                      // self-restore for next replay
        }
    }
}

extern "C" void kernel_launch(void* const* d_in, const int* in_sizes, int n_in,
                              void* d_out, int out_size) {
    const float* soft = (const float*)d_in[0];
    const int*   lab  = (const int*)d_in[1];
    const float* H    = (const float*)d_in[2];
    const float* cw   = (const float*)d_in[3];
    float* out = (float*)d_out;

    decode_kernel<<<BB / 2, 1024>>>(soft, lab, H, cw, out);
}